// round 6
// baseline (speedup 1.0000x reference)
#include <cuda_runtime.h>
#include <cstdint>

// Problem constants: R_MAX=32, S_MAX=2, C_Z=128, IN_FEATS=139
#define C_Z      128
#define IN_FEATS 139

// Global fused table layout (rows of 128 floats):
//   [0,66)    a rows:    Wt[dres]
//   [66,132)  b rows:    Wt[66+dtok]
//   [132,138) bc rows:   b_sent + c_ec              (b_sent = Wt[131])
//   [138,144) abc rows:  a_sent + b_sent + c_ec     (a_sent = Wt[65])
//   [144,150) a32c rows: a[32] + c_ec               (case ri==rj: dres==32)
//   (c_ec = ec<5 ? Wt[132]+Wt[133+ec] : Wt[138])
#define GROW_FUSED 132
#define GTAB_ROWS  150

// Shared table = the 18 fused rows (global rows 132..149):
//   [0,6) bc | [6,12) abc | [12,18) a32c
#define S_BC    0
#define S_ABC   6
#define S_A32C  12
#define S_ROWS  18

#define N_MAX   1024

// pk: s_row(bits 0-4) | G(bit 5) | g_row(bits 8-15)
#define PK_G    (1u << 5)

__device__ float g_tab[GTAB_ROWS * C_Z];

// ---------------------------------------------------------------------------
// Pre-kernel: build fused table. W: [C_Z, IN_FEATS] row-major,
// Wt[f][c] = W[c*IN_FEATS + f].
// ---------------------------------------------------------------------------
__global__ void build_tables_kernel(const float* __restrict__ W) {
    int r = blockIdx.x;          // 0..149
    int c = threadIdx.x;         // 0..127
    const float* wc = W + (size_t)c * IN_FEATS;

    float a_sent = wc[65];
    float b_sent = wc[131];
    float a32    = wc[32];

    float v;
    if (r < 132) {
        v = wc[r];                                   // a rows, b rows (verbatim)
    } else {
        int k = (r - 132) % 6;                       // ec class
        float ck = (k < 5) ? (wc[132] + wc[133 + k]) : wc[138];
        if      (r < 138) v = b_sent + ck;           // bc rows
        else if (r < 144) v = a_sent + b_sent + ck;  // abc rows
        else              v = a32 + ck;              // a32c rows
    }
    g_tab[r * C_Z + c] = v;
}

// ---------------------------------------------------------------------------
// Main kernel: one block per query row i; 256 threads = 8 warps.
// smem: 18 fused rows (9KB) + pk (4KB) => 8 CTAs/SM, single wave.
// Hot loop: 1 LDS.128 always, plus (28% of pairs) one L1-resident __ldg
// from the shared a/b table, one warp-uniform branch, STG.128 streaming store.
// ---------------------------------------------------------------------------
__global__ __launch_bounds__(256)
void relpos_kernel(const int* __restrict__ asym,
                   const int* __restrict__ resi,
                   const int* __restrict__ ent,
                   const int* __restrict__ sym,
                   const int* __restrict__ tok,
                   float* __restrict__ out,
                   int N) {
    __shared__ float    s_tab[S_ROWS * C_Z];   // 9216 B
    __shared__ unsigned s_pk[N_MAX];           // 4096 B

    // ---- copy the 18 fused rows (global rows 132..149) ----
    {
        const float4* src = (const float4*)(g_tab + GROW_FUSED * C_Z);
        float4*       dst = (float4*)s_tab;
        for (int k = threadIdx.x; k < S_ROWS * 32; k += blockDim.x)
            dst[k] = __ldg(src + k);
    }

    const int i = blockIdx.x;
    const int ai = asym[i], ri = resi[i], ei = ent[i], si = sym[i], ti = tok[i];

    // ---- phase 1: per-j packed indices (once per block) ----
    for (int j = threadIdx.x; j < N; j += blockDim.x) {
        const int aj = __ldg(asym + j);
        const int rj = __ldg(resi + j);
        const int ej = __ldg(ent  + j);
        const int sj = __ldg(sym  + j);
        const int tj = __ldg(tok  + j);

        int ec = (ei == ej) ? min(max(si - sj + 2, 0), 4) : 5;

        unsigned pk;
        if (ai != aj) {
            pk = (unsigned)(S_ABC + ec);                       // abc[ec] only
        } else if (ri != rj) {
            int dres = min(max(ri - rj + 32, 0), 64);
            pk = (unsigned)(S_BC + ec) | PK_G
               | ((unsigned)dres << 8);                        // bc[ec] + a[dres]
        } else {
            // dres == 32 exactly; a[32] folded into a32c[ec]
            int dtok = min(max(ti - tj + 32, 0), 64);
            pk = (unsigned)(S_A32C + ec) | PK_G
               | ((unsigned)(66 + dtok) << 8);                 // a32c[ec] + b[dtok]
        }
        s_pk[j] = pk;
    }
    __syncthreads();

    // ---- phase 2: 4 contiguous j's per warp sweep ----
    const int lane = threadIdx.x & 31;
    const int wid  = threadIdx.x >> 5;
    const float4* t4 = (const float4*)s_tab;                   // [18][32]
    const float4* g4 = (const float4*)g_tab;                   // [150][32]
    float* out_i = out + (size_t)i * N * C_Z;

    for (int j0 = wid * 4; j0 < N; j0 += 32) {
        #pragma unroll
        for (int u = 0; u < 4; u++) {
            const int j = j0 + u;
            const unsigned pk = s_pk[j];                       // warp-uniform

            float4 v = t4[(pk & 31) * 32 + lane];

            if (pk & PK_G) {                                   // ~28%, warp-uniform
                const int gr = (int)((pk >> 8) & 255);
                const float4 g = __ldg(g4 + gr * 32 + lane);
                v.x += g.x; v.y += g.y; v.z += g.z; v.w += g.w;
            }
            __stcs((float4*)(out_i + (size_t)j * C_Z) + lane, v);
        }
    }
}

extern "C" void kernel_launch(void* const* d_in, const int* in_sizes, int n_in,
                              void* d_out, int out_size) {
    const float* W    = (const float*)d_in[0];
    const int*   asym = (const int*)d_in[1];
    const int*   resi = (const int*)d_in[2];
    const int*   ent  = (const int*)d_in[3];
    const int*   sym  = (const int*)d_in[4];
    const int*   tok  = (const int*)d_in[5];
    float*       out  = (float*)d_out;

    const int N = in_sizes[1];   // 1024

    build_tables_kernel<<<GTAB_ROWS, C_Z>>>(W);
    relpos_kernel<<<N, 256>>>(asym, resi, ent, sym, tok, out, N);
}